// round 10
// baseline (speedup 1.0000x reference)
#include <cuda_runtime.h>

#define BATCH 8
#define SEQ 1024
#define HID 1024
#define D2 128
#define NHEADS 12
#define NC 24

typedef unsigned long long u64;

// ---------------- scratch (device globals; no allocation) ----------------
__device__ float g_qT[BATCH * 64 * SEQ];       // [b][d][s], pre-scaled by 1/8
__device__ float g_kT[BATCH * 64 * SEQ];       // [b][d][s]
__device__ float g_bias[BATCH * NC * SEQ];     // [b][c][s], already (h@W2+b2)/2

// ---------------- f32x2 helpers ----------------
__device__ __forceinline__ u64 pack2(float lo, float hi) {
    u64 r; asm("mov.b64 %0, {%1,%2};" : "=l"(r) : "f"(lo), "f"(hi)); return r;
}
__device__ __forceinline__ void unpack2(u64 v, float& lo, float& hi) {
    asm("mov.b64 {%0,%1}, %2;" : "=f"(lo), "=f"(hi) : "l"(v));
}
__device__ __forceinline__ void fma2(u64& d, u64 a, u64 b) {
    asm("fma.rn.f32x2 %0, %1, %2, %0;" : "+l"(d) : "l"(a), "l"(b));
}

// ---------------- cp.async helpers ----------------
__device__ __forceinline__ void cpa16(void* s, const void* g) {
    unsigned sa = (unsigned)__cvta_generic_to_shared(s);
    asm volatile("cp.async.cg.shared.global [%0], [%1], 16;\n" :: "r"(sa), "l"(g));
}
__device__ __forceinline__ void cpa_commit() { asm volatile("cp.async.commit_group;\n" ::: "memory"); }
template<int N> __device__ __forceinline__ void cpa_wait() {
    asm volatile("cp.async.wait_group %0;\n" :: "n"(N) : "memory");
}

// ---------------- tf32 mma ----------------
__device__ __forceinline__ void mma_tf32(float* d, const unsigned* a, const unsigned* b) {
    asm volatile("mma.sync.aligned.m16n8k8.row.col.f32.tf32.tf32.f32 "
        "{%0,%1,%2,%3}, {%4,%5,%6,%7}, {%8,%9}, {%0,%1,%2,%3};"
        : "+f"(d[0]), "+f"(d[1]), "+f"(d[2]), "+f"(d[3])
        : "r"(a[0]), "r"(a[1]), "r"(a[2]), "r"(a[3]), "r"(b[0]), "r"(b[1]));
}

// smem geometry (floats) — M-tile 64, 512 threads
#define AROW 36
#define BROW 136
#define A_ST (64 * AROW)            // 2304
#define B_ST (32 * BROW)            // 4352
#define NBUF 3
#define SMEM_FLOATS (NBUF * (A_ST + B_ST))   // 19968 floats = 79872 B
#define HROW 132

// -1e12 in fp32 = -999999995904; adding |x|<32768 rounds back to it exactly.
#define CBIG -999999995904.0f

// ---------------- fill kernel: fully-masked lower tiles -> constant (0 smem) ----------------
__global__ __launch_bounds__(256) void fill_kernel(const float* __restrict__ am,
                                                   float* __restrict__ out) {
    const int fid = blockIdx.x;
    const int b = fid / 120;
    int r = fid % 120;
    int mt = (int)((1.0f + sqrtf(8.0f * r + 1.0f)) * 0.5f);
    while (mt * (mt - 1) / 2 > r) mt--;
    while ((mt + 1) * mt / 2 <= r) mt++;
    const int nt = r - mt * (mt - 1) / 2;          // nt < mt
    const int m0 = mt * 64, n0 = nt * 64;

    const int t = threadIdx.x;
    bool ok = true;
    if (t < 128) {
        float v = (t < 64) ? am[b * SEQ + m0 + t] : am[b * SEQ + n0 + (t - 64)];
        ok = (v == 1.0f);
    }
    if (!__syncthreads_and(ok)) return;            // masked: logits kernel handles it

    const float4 C4 = make_float4(CBIG, CBIG, CBIG, CBIG);
    const int m = t >> 4, n = (t & 15) * 4;
#pragma unroll
    for (int h = 0; h < NHEADS; h++) {
        size_t base = (((size_t)(b * NHEADS + h)) * SEQ + m0) * SEQ + n0;
#pragma unroll
        for (int i = 0; i < 4; i++)
            __stcs((float4*)(out + base + (size_t)(m + 16 * i) * SEQ + n), C4);
    }
}

// ---------------- kernel 1: fused h=X@W1+b1 -> RoPE(q,k)T + bias ----------------
// 512 threads (16 warps, 4m x 4n; warp tile 16x32), M-tile 64, K staged x32, 3-deep pipeline.
__global__ __launch_bounds__(512) void gemm_rope_kernel(const float* __restrict__ X,
                                                        const float* __restrict__ W1,
                                                        const float* __restrict__ b1,
                                                        const float* __restrict__ W2,
                                                        const float* __restrict__ b2) {
    extern __shared__ float smem[];
    float* Abase = smem;                    // NBUF x [64][AROW]
    float* Bbase = smem + NBUF * A_ST;      // NBUF x [32][BROW]

    const int t = threadIdx.x;
    const int m0 = blockIdx.x * 64;         // global row base (b*1024 + s0)
    const int warp = t >> 5, lane = t & 31;
    const int g = lane >> 2, tg = lane & 3;
    const int wm = (warp & 3) * 16;         // warp m offset
    const int wn = (warp >> 2) * 32;        // warp n offset

    const int a_r = t >> 3, a_c = (t & 7) * 4;     // A: 64x32 = 512 chunks, 1/thread
    const int b_r = t >> 5, b_c = (t & 31) * 4;    // B: 32x128 = 1024 chunks, 2/thread

    auto load_stage = [&](int buf, int s) {
        const int k0 = s * 32;
        float* A = Abase + buf * A_ST;
        float* B = Bbase + buf * B_ST;
        cpa16(&A[a_r * AROW + a_c], &X[(size_t)(m0 + a_r) * HID + k0 + a_c]);
        cpa16(&B[b_r * BROW + b_c],        &W1[(size_t)(k0 + b_r) * D2 + b_c]);
        cpa16(&B[(b_r + 16) * BROW + b_c], &W1[(size_t)(k0 + b_r + 16) * D2 + b_c]);
        cpa_commit();
    };

    float acc[4][4];    // [n8][frag] — warp tile m16 x n32
#pragma unroll
    for (int ni = 0; ni < 4; ni++) {
        float blo = b1[wn + ni * 8 + 2 * tg];
        float bhi = b1[wn + ni * 8 + 2 * tg + 1];
        acc[ni][0] = blo; acc[ni][1] = bhi;
        acc[ni][2] = blo; acc[ni][3] = bhi;
    }

    const int NS = HID / 32;   // 32 stages
    load_stage(0, 0);
    load_stage(1, 1);

    for (int s = 0; s < NS; s++) {
        if (s + 2 < NS) { load_stage((s + 2) % 3, s + 2); cpa_wait<2>(); }
        else if (s + 1 < NS) cpa_wait<1>();
        else cpa_wait<0>();
        __syncthreads();

        const float* A = Abase + (s % 3) * A_ST;
        const float* B = Bbase + (s % 3) * B_ST;
#pragma unroll
        for (int kk = 0; kk < 32; kk += 8) {
            unsigned af[4];
            af[0] = __float_as_uint(A[(wm + g) * AROW + kk + tg]);
            af[1] = __float_as_uint(A[(wm + g + 8) * AROW + kk + tg]);
            af[2] = __float_as_uint(A[(wm + g) * AROW + kk + tg + 4]);
            af[3] = __float_as_uint(A[(wm + g + 8) * AROW + kk + tg + 4]);
            unsigned bf[4][2];
#pragma unroll
            for (int ni = 0; ni < 4; ni++) {
                const int nn = wn + ni * 8 + g;
                bf[ni][0] = __float_as_uint(B[(kk + tg) * BROW + nn]);
                bf[ni][1] = __float_as_uint(B[(kk + tg + 4) * BROW + nn]);
            }
#pragma unroll
            for (int ni = 0; ni < 4; ni++)
                mma_tf32(acc[ni], af, bf[ni]);
        }
        __syncthreads();
    }

    // -------- epilogue: stash h tile in smem (reuse stage buffers) --------
    float* hs = smem;                 // [64][HROW]
    float* ws = smem + 64 * HROW;     // [128*24] W2
    __syncthreads();

#pragma unroll
    for (int ni = 0; ni < 4; ni++) {
        const int row = wm + g;
        const int col = wn + ni * 8 + 2 * tg;
        *(float2*)&hs[row * HROW + col]       = make_float2(acc[ni][0], acc[ni][1]);
        *(float2*)&hs[(row + 8) * HROW + col] = make_float2(acc[ni][2], acc[ni][3]);
    }
#pragma unroll
    for (int u = 0; u < 6; u++) ws[t + 512 * u] = W2[t + 512 * u];
    __syncthreads();

    const int b = m0 >> 10;
    const int s0 = m0 & 1023;
    const int sl = t & 63;            // row within tile
    const int dg = t >> 6;            // 0..7
    const int s = s0 + sl;
    const float* hrow = &hs[sl * HROW];

#pragma unroll
    for (int it = 0; it < 8; it++) {
        int d = dg + it * 8;          // 0..63
        int j = d >> 1;
        float inv = exp2f((float)(2 * j) * (-13.287712379549449f / 64.0f));
        float ang = (float)s * inv;
        float sn, cs;
        sincosf(ang, &sn, &cs);
        float qA = hrow[4 * j],     qB = hrow[4 * j + 2];
        float kA = hrow[4 * j + 1], kB = hrow[4 * j + 3];
        float qv, kv;
        if (d & 1) { qv = qB * cs + qA * sn; kv = kB * cs + kA * sn; }
        else       { qv = qA * cs - qB * sn; kv = kA * cs - kB * sn; }
        g_qT[(size_t)(b * 64 + d) * SEQ + s] = qv * 0.125f;   // fold 1/sqrt(64)
        g_kT[(size_t)(b * 64 + d) * SEQ + s] = kv;
    }

#pragma unroll
    for (int it = 0; it < 3; it++) {
        int cc = dg + it * 8;         // 0..23
        float dot = b2[cc];
#pragma unroll
        for (int j = 0; j < D2; j += 4) {
            float4 h4 = *(const float4*)&hrow[j];
            dot += h4.x * ws[(j + 0) * NC + cc] + h4.y * ws[(j + 1) * NC + cc]
                 + h4.z * ws[(j + 2) * NC + cc] + h4.w * ws[(j + 3) * NC + cc];
        }
        g_bias[(size_t)(b * NC + cc) * SEQ + s] = dot * 0.5f;
    }
}

// ---------------- kernel 2: logits (early-exit prefilled tiles + compute) ----------------
__global__ __launch_bounds__(256) void logits_kernel(const float* __restrict__ am,
                                                     float* __restrict__ out) {
    __shared__ float qs[64][64];
    __shared__ float ks[64][64];
    __shared__ float bq[NHEADS][64];
    __shared__ float bk[NHEADS][64];
    __shared__ float amm[64], amn[64];
    __shared__ int s_maskone;

    const int t = threadIdx.x;
    const int b = blockIdx.z, mt = blockIdx.y, nt = blockIdx.x;
    const int m0 = mt * 64, n0 = nt * 64;
    const int tm = t >> 4, tn = t & 15;
    const int ml = tm * 4, nl = tn * 4;

    if (t == 0) s_maskone = 1;
    if (t < 16)      *(float4*)&amm[t * 4]        = *(const float4*)&am[b * SEQ + m0 + t * 4];
    else if (t < 32) *(float4*)&amn[(t - 16) * 4] = *(const float4*)&am[b * SEQ + n0 + (t - 16) * 4];
    __syncthreads();
    if (t < 64 && (amm[t] != 1.0f || amn[t] != 1.0f)) s_maskone = 0;
    __syncthreads();
    const int maskone = s_maskone;

    // fully-masked lower tile: already written by fill_kernel
    if (maskone && m0 > n0 + 63) return;

    // ---------- slow path ----------
#pragma unroll
    for (int u = 0; u < 4; u++) {
        int idx = t + 256 * u;
        int d = idx >> 4, mq = (idx & 15) * 4;
        *(float4*)&qs[d][mq] = *(const float4*)&g_qT[(size_t)(b * 64 + d) * SEQ + m0 + mq];
        *(float4*)&ks[d][mq] = *(const float4*)&g_kT[(size_t)(b * 64 + d) * SEQ + n0 + mq];
    }
    if (t < 192) {
        int h = t >> 4, mq = (t & 15) * 4;
        *(float4*)&bq[h][mq] = *(const float4*)&g_bias[(size_t)(b * NC + 2 * h) * SEQ + m0 + mq];
        *(float4*)&bk[h][mq] = *(const float4*)&g_bias[(size_t)(b * NC + 2 * h + 1) * SEQ + n0 + mq];
    }
    __syncthreads();

    u64 acc[4][2];
    u64 z = pack2(0.0f, 0.0f);
#pragma unroll
    for (int i = 0; i < 4; i++) { acc[i][0] = z; acc[i][1] = z; }

#pragma unroll 8
    for (int d = 0; d < 64; d++) {
        float4 q4 = *(float4*)&qs[d][ml];
        ulonglong2 kp = *(const ulonglong2*)&ks[d][nl];
        u64 q0 = pack2(q4.x, q4.x), q1 = pack2(q4.y, q4.y);
        u64 q2 = pack2(q4.z, q4.z), q3 = pack2(q4.w, q4.w);
        fma2(acc[0][0], q0, kp.x); fma2(acc[0][1], q0, kp.y);
        fma2(acc[1][0], q1, kp.x); fma2(acc[1][1], q1, kp.y);
        fma2(acc[2][0], q2, kp.x); fma2(acc[2][1], q2, kp.y);
        fma2(acc[3][0], q3, kp.x); fma2(acc[3][1], q3, kp.y);
    }

    float att[4][4];
#pragma unroll
    for (int i = 0; i < 4; i++) {
        unpack2(acc[i][0], att[i][0], att[i][1]);
        unpack2(acc[i][1], att[i][2], att[i][3]);
    }

    const float BIG = 1e12f;
#pragma unroll
    for (int i = 0; i < 4; i++) {
        int gm = m0 + ml + i;
#pragma unroll
        for (int j = 0; j < 4; j++) {
            int gn = n0 + nl + j;
            if (!maskone) att[i][j] -= (1.0f - amm[ml + i] * amn[nl + j]) * BIG;
            if (gm > gn) att[i][j] -= BIG;
        }
    }

    const bool rowzero = (m0 == 0 && tm == 0);
    const bool colzero = (n0 == 0 && tn == 0);
    const float NEG = -10000.0f;

    for (int h = 0; h < NHEADS; h++) {
        size_t base = (((size_t)(b * NHEADS + h)) * SEQ + m0) * SEQ + n0;
        float4 bkv = *(float4*)&bk[h][nl];
#pragma unroll
        for (int i = 0; i < 4; i++) {
            float bb = bq[h][ml + i];
            float4 v;
            v.x = att[i][0] + bb + bkv.x;
            v.y = att[i][1] + bb + bkv.y;
            v.z = att[i][2] + bb + bkv.z;
            v.w = att[i][3] + bb + bkv.w;
            if (rowzero && i == 0) { v.x = NEG; v.y = NEG; v.z = NEG; v.w = NEG; }
            if (colzero) v.x = (m0 + ml + i == 0) ? NEG : CBIG;
            __stcs((float4*)(out + base + (size_t)(ml + i) * SEQ + nl), v);
        }
    }
}

// ---------------- launch ----------------
extern "C" void kernel_launch(void* const* d_in, const int* in_sizes, int n_in,
                              void* d_out, int out_size) {
    const float* X  = (const float*)d_in[0];
    const float* am = (const float*)d_in[1];
    const float* W1 = (const float*)d_in[2];
    const float* b1 = (const float*)d_in[3];
    const float* W2 = (const float*)d_in[4];
    const float* b2 = (const float*)d_in[5];
    float* out = (float*)d_out;

    // lazily-created side stream + events (created on the first, uncaptured,
    // correctness call; the enqueued work is identical on every call)
    static cudaStream_t s2 = 0;
    static cudaEvent_t evFork = 0, evJoin = 0;
    static int init_ok = -1;
    if (init_ok < 0) {
        init_ok = (cudaStreamCreateWithFlags(&s2, cudaStreamNonBlocking) == cudaSuccess &&
                   cudaEventCreateWithFlags(&evFork, cudaEventDisableTiming) == cudaSuccess &&
                   cudaEventCreateWithFlags(&evJoin, cudaEventDisableTiming) == cudaSuccess) ? 1 : 0;
        cudaFuncSetAttribute(gemm_rope_kernel,
                             cudaFuncAttributeMaxDynamicSharedMemorySize,
                             SMEM_FLOATS * 4);
    }

    if (init_ok) {
        // fork: fill runs concurrently with the GEMM prologue
        cudaEventRecord(evFork, 0);
        cudaStreamWaitEvent(s2, evFork, 0);
        fill_kernel<<<BATCH * 120, 256, 0, s2>>>(am, out);
        gemm_rope_kernel<<<(BATCH * SEQ) / 64, 512, SMEM_FLOATS * 4>>>(X, W1, b1, W2, b2);
        cudaEventRecord(evJoin, s2);
        cudaStreamWaitEvent(0, evJoin, 0);
    } else {
        fill_kernel<<<BATCH * 120, 256>>>(am, out);
        gemm_rope_kernel<<<(BATCH * SEQ) / 64, 512, SMEM_FLOATS * 4>>>(X, W1, b1, W2, b2);
    }
    dim3 g3(SEQ / 64, SEQ / 64, BATCH);
    logits_kernel<<<g3, 256>>>(am, out);
}

// round 11
// speedup vs baseline: 1.1228x; 1.1228x over previous
#include <cuda_runtime.h>
#include <cuda_bf16.h>

#define BATCH 8
#define SEQ 1024
#define HID 1024
#define D2 128
#define NHEADS 12
#define NC 24

typedef unsigned long long u64;

// ---------------- scratch (device globals; no allocation) ----------------
__device__ __nv_bfloat16 g_qT[BATCH * 64 * SEQ];    // [b][d][s], pre-scaled by 1/8
__device__ __nv_bfloat16 g_kT[BATCH * 64 * SEQ];    // [b][d][s]
__device__ __nv_bfloat16 g_bias[BATCH * NC * SEQ];  // [b][c][s], already (h@W2+b2)/2

// ---------------- f32x2 helpers ----------------
__device__ __forceinline__ u64 pack2(float lo, float hi) {
    u64 r; asm("mov.b64 %0, {%1,%2};" : "=l"(r) : "f"(lo), "f"(hi)); return r;
}
__device__ __forceinline__ void unpack2(u64 v, float& lo, float& hi) {
    asm("mov.b64 {%0,%1}, %2;" : "=f"(lo), "=f"(hi) : "l"(v));
}
__device__ __forceinline__ void fma2(u64& d, u64 a, u64 b) {
    asm("fma.rn.f32x2 %0, %1, %2, %0;" : "+l"(d) : "l"(a), "l"(b));
}

// ---------------- cp.async helpers ----------------
__device__ __forceinline__ void cpa16(void* s, const void* g) {
    unsigned sa = (unsigned)__cvta_generic_to_shared(s);
    asm volatile("cp.async.cg.shared.global [%0], [%1], 16;\n" :: "r"(sa), "l"(g));
}
__device__ __forceinline__ void cpa_commit() { asm volatile("cp.async.commit_group;\n" ::: "memory"); }
template<int N> __device__ __forceinline__ void cpa_wait() {
    asm volatile("cp.async.wait_group %0;\n" :: "n"(N) : "memory");
}

// ---------------- tf32 mma ----------------
__device__ __forceinline__ void mma_tf32(float* d, const unsigned* a, const unsigned* b) {
    asm volatile("mma.sync.aligned.m16n8k8.row.col.f32.tf32.tf32.f32 "
        "{%0,%1,%2,%3}, {%4,%5,%6,%7}, {%8,%9}, {%0,%1,%2,%3};"
        : "+f"(d[0]), "+f"(d[1]), "+f"(d[2]), "+f"(d[3])
        : "r"(a[0]), "r"(a[1]), "r"(a[2]), "r"(a[3]), "r"(b[0]), "r"(b[1]));
}

// bf16x4 (as uint2) -> float4
__device__ __forceinline__ float4 bf4_to_f4(uint2 v) {
    __nv_bfloat162 p0 = *reinterpret_cast<__nv_bfloat162*>(&v.x);
    __nv_bfloat162 p1 = *reinterpret_cast<__nv_bfloat162*>(&v.y);
    float2 f0 = __bfloat1622float2(p0);
    float2 f1 = __bfloat1622float2(p1);
    return make_float4(f0.x, f0.y, f1.x, f1.y);
}

// smem geometry (floats) — M-tile 64, 512 threads
#define AROW 36
#define BROW 136
#define A_ST (64 * AROW)            // 2304
#define B_ST (32 * BROW)            // 4352
#define NBUF 3
#define SMEM_FLOATS (NBUF * (A_ST + B_ST))   // 19968 floats = 79872 B
#define HROW 132

// -1e12 in fp32 = -999999995904; adding |x|<32768 rounds back to it exactly.
#define CBIG -999999995904.0f

// ---------------- kernel 1: fused h=X@W1+b1 -> RoPE(q,k)T + bias (bf16 out) ----------------
// 512 threads (16 warps, 4m x 4n; warp tile 16x32), M-tile 64, K staged x32, 3-deep pipeline.
__global__ __launch_bounds__(512) void gemm_rope_kernel(const float* __restrict__ X,
                                                        const float* __restrict__ W1,
                                                        const float* __restrict__ b1,
                                                        const float* __restrict__ W2,
                                                        const float* __restrict__ b2) {
    extern __shared__ float smem[];
    float* Abase = smem;                    // NBUF x [64][AROW]
    float* Bbase = smem + NBUF * A_ST;      // NBUF x [32][BROW]

    const int t = threadIdx.x;
    const int m0 = blockIdx.x * 64;         // global row base (b*1024 + s0)
    const int warp = t >> 5, lane = t & 31;
    const int g = lane >> 2, tg = lane & 3;
    const int wm = (warp & 3) * 16;         // warp m offset
    const int wn = (warp >> 2) * 32;        // warp n offset

    const int a_r = t >> 3, a_c = (t & 7) * 4;     // A: 64x32 = 512 chunks, 1/thread
    const int b_r = t >> 5, b_c = (t & 31) * 4;    // B: 32x128 = 1024 chunks, 2/thread

    auto load_stage = [&](int buf, int s) {
        const int k0 = s * 32;
        float* A = Abase + buf * A_ST;
        float* B = Bbase + buf * B_ST;
        cpa16(&A[a_r * AROW + a_c], &X[(size_t)(m0 + a_r) * HID + k0 + a_c]);
        cpa16(&B[b_r * BROW + b_c],        &W1[(size_t)(k0 + b_r) * D2 + b_c]);
        cpa16(&B[(b_r + 16) * BROW + b_c], &W1[(size_t)(k0 + b_r + 16) * D2 + b_c]);
        cpa_commit();
    };

    float acc[4][4];    // [n8][frag] — warp tile m16 x n32
#pragma unroll
    for (int ni = 0; ni < 4; ni++) {
        float blo = b1[wn + ni * 8 + 2 * tg];
        float bhi = b1[wn + ni * 8 + 2 * tg + 1];
        acc[ni][0] = blo; acc[ni][1] = bhi;
        acc[ni][2] = blo; acc[ni][3] = bhi;
    }

    const int NS = HID / 32;   // 32 stages
    load_stage(0, 0);
    load_stage(1, 1);

    for (int s = 0; s < NS; s++) {
        if (s + 2 < NS) { load_stage((s + 2) % 3, s + 2); cpa_wait<2>(); }
        else if (s + 1 < NS) cpa_wait<1>();
        else cpa_wait<0>();
        __syncthreads();

        const float* A = Abase + (s % 3) * A_ST;
        const float* B = Bbase + (s % 3) * B_ST;
#pragma unroll
        for (int kk = 0; kk < 32; kk += 8) {
            unsigned af[4];
            af[0] = __float_as_uint(A[(wm + g) * AROW + kk + tg]);
            af[1] = __float_as_uint(A[(wm + g + 8) * AROW + kk + tg]);
            af[2] = __float_as_uint(A[(wm + g) * AROW + kk + tg + 4]);
            af[3] = __float_as_uint(A[(wm + g + 8) * AROW + kk + tg + 4]);
            unsigned bf[4][2];
#pragma unroll
            for (int ni = 0; ni < 4; ni++) {
                const int nn = wn + ni * 8 + g;
                bf[ni][0] = __float_as_uint(B[(kk + tg) * BROW + nn]);
                bf[ni][1] = __float_as_uint(B[(kk + tg + 4) * BROW + nn]);
            }
#pragma unroll
            for (int ni = 0; ni < 4; ni++)
                mma_tf32(acc[ni], af, bf[ni]);
        }
        __syncthreads();
    }

    // -------- epilogue: stash h tile in smem (reuse stage buffers) --------
    float* hs = smem;                 // [64][HROW]
    float* ws = smem + 64 * HROW;     // [128*24] W2
    __syncthreads();

#pragma unroll
    for (int ni = 0; ni < 4; ni++) {
        const int row = wm + g;
        const int col = wn + ni * 8 + 2 * tg;
        *(float2*)&hs[row * HROW + col]       = make_float2(acc[ni][0], acc[ni][1]);
        *(float2*)&hs[(row + 8) * HROW + col] = make_float2(acc[ni][2], acc[ni][3]);
    }
#pragma unroll
    for (int u = 0; u < 6; u++) ws[t + 512 * u] = W2[t + 512 * u];
    __syncthreads();

    const int b = m0 >> 10;
    const int s0 = m0 & 1023;
    const int sl = t & 63;            // row within tile
    const int dg = t >> 6;            // 0..7
    const int s = s0 + sl;
    const float* hrow = &hs[sl * HROW];

#pragma unroll
    for (int it = 0; it < 8; it++) {
        int d = dg + it * 8;          // 0..63
        int j = d >> 1;
        float inv = exp2f((float)(2 * j) * (-13.287712379549449f / 64.0f));
        float ang = (float)s * inv;
        float sn, cs;
        sincosf(ang, &sn, &cs);
        float qA = hrow[4 * j],     qB = hrow[4 * j + 2];
        float kA = hrow[4 * j + 1], kB = hrow[4 * j + 3];
        float qv, kv;
        if (d & 1) { qv = qB * cs + qA * sn; kv = kB * cs + kA * sn; }
        else       { qv = qA * cs - qB * sn; kv = kA * cs - kB * sn; }
        g_qT[(size_t)(b * 64 + d) * SEQ + s] = __float2bfloat16(qv * 0.125f);  // fold 1/sqrt(64)
        g_kT[(size_t)(b * 64 + d) * SEQ + s] = __float2bfloat16(kv);
    }

#pragma unroll
    for (int it = 0; it < 3; it++) {
        int cc = dg + it * 8;         // 0..23
        float dot = b2[cc];
#pragma unroll
        for (int j = 0; j < D2; j += 4) {
            float4 h4 = *(const float4*)&hrow[j];
            dot += h4.x * ws[(j + 0) * NC + cc] + h4.y * ws[(j + 1) * NC + cc]
                 + h4.z * ws[(j + 2) * NC + cc] + h4.w * ws[(j + 3) * NC + cc];
        }
        g_bias[(size_t)(b * NC + cc) * SEQ + s] = __float2bfloat16(dot * 0.5f);
    }
}

// ---------------- kernel 2: logits (fill fast path + compute), bf16 staging ----------------
__global__ __launch_bounds__(256) void logits_kernel(const float* __restrict__ am,
                                                     float* __restrict__ out) {
    __shared__ float qs[64][64];
    __shared__ float ks[64][64];
    __shared__ float bq[NHEADS][64];
    __shared__ float bk[NHEADS][64];
    __shared__ float amm[64], amn[64];
    __shared__ int s_maskone;

    const int t = threadIdx.x;
    const int b = blockIdx.z, mt = blockIdx.y, nt = blockIdx.x;
    const int m0 = mt * 64, n0 = nt * 64;
    const int tm = t >> 4, tn = t & 15;
    const int ml = tm * 4, nl = tn * 4;

    if (t == 0) s_maskone = 1;
    if (t < 16)      *(float4*)&amm[t * 4]        = *(const float4*)&am[b * SEQ + m0 + t * 4];
    else if (t < 32) *(float4*)&amn[(t - 16) * 4] = *(const float4*)&am[b * SEQ + n0 + (t - 16) * 4];
    __syncthreads();
    if (t < 64 && (amm[t] != 1.0f || amn[t] != 1.0f)) s_maskone = 0;
    __syncthreads();
    const int maskone = s_maskone;

    // ---------- fast path: fully-masked tile -> constant ----------
    if (maskone && m0 > n0 + 63) {
        const float4 C4 = make_float4(CBIG, CBIG, CBIG, CBIG);
        for (int h = 0; h < NHEADS; h++) {
            size_t base = (((size_t)(b * NHEADS + h)) * SEQ + m0) * SEQ + n0;
#pragma unroll
            for (int i = 0; i < 4; i++) {
                int idx = t + 256 * i;
                int m = idx >> 4, n = (idx & 15) * 4;
                __stcs((float4*)(out + base + (size_t)m * SEQ + n), C4);
            }
        }
        return;
    }

    // ---------- slow path: stage bf16 -> fp32 smem ----------
#pragma unroll
    for (int u = 0; u < 4; u++) {
        int idx = t + 256 * u;
        int d = idx >> 4, mq = (idx & 15) * 4;
        uint2 qv = *(const uint2*)&g_qT[(size_t)(b * 64 + d) * SEQ + m0 + mq];
        uint2 kv = *(const uint2*)&g_kT[(size_t)(b * 64 + d) * SEQ + n0 + mq];
        *(float4*)&qs[d][mq] = bf4_to_f4(qv);
        *(float4*)&ks[d][mq] = bf4_to_f4(kv);
    }
    if (t < 192) {
        int h = t >> 4, mq = (t & 15) * 4;
        uint2 bqv = *(const uint2*)&g_bias[(size_t)(b * NC + 2 * h) * SEQ + m0 + mq];
        uint2 bkv = *(const uint2*)&g_bias[(size_t)(b * NC + 2 * h + 1) * SEQ + n0 + mq];
        *(float4*)&bq[h][mq] = bf4_to_f4(bqv);
        *(float4*)&bk[h][mq] = bf4_to_f4(bkv);
    }
    __syncthreads();

    u64 acc[4][2];
    u64 z = pack2(0.0f, 0.0f);
#pragma unroll
    for (int i = 0; i < 4; i++) { acc[i][0] = z; acc[i][1] = z; }

#pragma unroll 8
    for (int d = 0; d < 64; d++) {
        float4 q4 = *(float4*)&qs[d][ml];
        ulonglong2 kp = *(const ulonglong2*)&ks[d][nl];
        u64 q0 = pack2(q4.x, q4.x), q1 = pack2(q4.y, q4.y);
        u64 q2 = pack2(q4.z, q4.z), q3 = pack2(q4.w, q4.w);
        fma2(acc[0][0], q0, kp.x); fma2(acc[0][1], q0, kp.y);
        fma2(acc[1][0], q1, kp.x); fma2(acc[1][1], q1, kp.y);
        fma2(acc[2][0], q2, kp.x); fma2(acc[2][1], q2, kp.y);
        fma2(acc[3][0], q3, kp.x); fma2(acc[3][1], q3, kp.y);
    }

    float att[4][4];
#pragma unroll
    for (int i = 0; i < 4; i++) {
        unpack2(acc[i][0], att[i][0], att[i][1]);
        unpack2(acc[i][1], att[i][2], att[i][3]);
    }

    const float BIG = 1e12f;
#pragma unroll
    for (int i = 0; i < 4; i++) {
        int gm = m0 + ml + i;
#pragma unroll
        for (int j = 0; j < 4; j++) {
            int gn = n0 + nl + j;
            if (!maskone) att[i][j] -= (1.0f - amm[ml + i] * amn[nl + j]) * BIG;
            if (gm > gn) att[i][j] -= BIG;
        }
    }

    const bool rowzero = (m0 == 0 && tm == 0);
    const bool colzero = (n0 == 0 && tn == 0);
    const float NEG = -10000.0f;

    for (int h = 0; h < NHEADS; h++) {
        size_t base = (((size_t)(b * NHEADS + h)) * SEQ + m0) * SEQ + n0;
        float4 bkv = *(float4*)&bk[h][nl];
#pragma unroll
        for (int i = 0; i < 4; i++) {
            float bb = bq[h][ml + i];
            float4 v;
            v.x = att[i][0] + bb + bkv.x;
            v.y = att[i][1] + bb + bkv.y;
            v.z = att[i][2] + bb + bkv.z;
            v.w = att[i][3] + bb + bkv.w;
            if (rowzero && i == 0) { v.x = NEG; v.y = NEG; v.z = NEG; v.w = NEG; }
            if (colzero) v.x = (m0 + ml + i == 0) ? NEG : CBIG;
            __stcs((float4*)(out + base + (size_t)(ml + i) * SEQ + nl), v);
        }
    }
}

// ---------------- launch ----------------
extern "C" void kernel_launch(void* const* d_in, const int* in_sizes, int n_in,
                              void* d_out, int out_size) {
    const float* X  = (const float*)d_in[0];
    const float* am = (const float*)d_in[1];
    const float* W1 = (const float*)d_in[2];
    const float* b1 = (const float*)d_in[3];
    const float* W2 = (const float*)d_in[4];
    const float* b2 = (const float*)d_in[5];
    float* out = (float*)d_out;

    cudaFuncSetAttribute(gemm_rope_kernel,
                         cudaFuncAttributeMaxDynamicSharedMemorySize,
                         SMEM_FLOATS * 4);
    gemm_rope_kernel<<<(BATCH * SEQ) / 64, 512, SMEM_FLOATS * 4>>>(X, W1, b1, W2, b2);
    dim3 g3(SEQ / 64, SEQ / 64, BATCH);
    logits_kernel<<<g3, 256>>>(am, out);
}

// round 12
// speedup vs baseline: 1.1949x; 1.0643x over previous
#include <cuda_runtime.h>
#include <cuda_bf16.h>

#define BATCH 8
#define SEQ 1024
#define HID 1024
#define D2 128
#define NHEADS 12
#define NC 24

typedef unsigned long long u64;

// ---------------- scratch (device globals; no allocation) ----------------
__device__ __nv_bfloat16 g_qT[BATCH * 64 * SEQ];    // [b][d][s], pre-scaled by 1/8
__device__ __nv_bfloat16 g_kT[BATCH * 64 * SEQ];    // [b][d][s]
__device__ __nv_bfloat16 g_bias[BATCH * NC * SEQ];  // [b][c][s], already (h@W2+b2)/2

// ---------------- f32x2 helpers ----------------
__device__ __forceinline__ u64 pack2(float lo, float hi) {
    u64 r; asm("mov.b64 %0, {%1,%2};" : "=l"(r) : "f"(lo), "f"(hi)); return r;
}
__device__ __forceinline__ void unpack2(u64 v, float& lo, float& hi) {
    asm("mov.b64 {%0,%1}, %2;" : "=f"(lo), "=f"(hi) : "l"(v));
}
__device__ __forceinline__ void fma2(u64& d, u64 a, u64 b) {
    asm("fma.rn.f32x2 %0, %1, %2, %0;" : "+l"(d) : "l"(a), "l"(b));
}

// ---------------- cp.async helpers ----------------
__device__ __forceinline__ void cpa16(void* s, const void* g) {
    unsigned sa = (unsigned)__cvta_generic_to_shared(s);
    asm volatile("cp.async.cg.shared.global [%0], [%1], 16;\n" :: "r"(sa), "l"(g));
}
__device__ __forceinline__ void cpa_commit() { asm volatile("cp.async.commit_group;\n" ::: "memory"); }
template<int N> __device__ __forceinline__ void cpa_wait() {
    asm volatile("cp.async.wait_group %0;\n" :: "n"(N) : "memory");
}

// ---------------- tf32 mma ----------------
__device__ __forceinline__ void mma_tf32(float* d, const unsigned* a, const unsigned* b) {
    asm volatile("mma.sync.aligned.m16n8k8.row.col.f32.tf32.tf32.f32 "
        "{%0,%1,%2,%3}, {%4,%5,%6,%7}, {%8,%9}, {%0,%1,%2,%3};"
        : "+f"(d[0]), "+f"(d[1]), "+f"(d[2]), "+f"(d[3])
        : "r"(a[0]), "r"(a[1]), "r"(a[2]), "r"(a[3]), "r"(b[0]), "r"(b[1]));
}

// bf16x4 (as uint2) -> float4
__device__ __forceinline__ float4 bf4_to_f4(uint2 v) {
    __nv_bfloat162 p0 = *reinterpret_cast<__nv_bfloat162*>(&v.x);
    __nv_bfloat162 p1 = *reinterpret_cast<__nv_bfloat162*>(&v.y);
    float2 f0 = __bfloat1622float2(p0);
    float2 f1 = __bfloat1622float2(p1);
    return make_float4(f0.x, f0.y, f1.x, f1.y);
}

// smem geometry (floats) — M-tile 64, 256 threads, NBUF=4 (round-4/5 champion geometry)
#define AROW 36
#define BROW 136
#define A_ST (64 * AROW)            // 2304
#define B_ST (32 * BROW)            // 4352
#define NBUF 4
#define SMEM_FLOATS (NBUF * (A_ST + B_ST))   // 26624 floats = 106496 B
#define HROW 132

// -1e12 in fp32 = -999999995904; adding |x|<32768 rounds back to it exactly.
#define CBIG -999999995904.0f

// ---------------- kernel 1: fused h=X@W1+b1 -> RoPE(q,k)T + bias (bf16 out) ----------------
// 256 threads (8 warps, 2m x 4n; warp tile 32x32), M-tile 64, K staged x32, 4-deep pipeline.
__global__ __launch_bounds__(256) void gemm_rope_kernel(const float* __restrict__ X,
                                                        const float* __restrict__ W1,
                                                        const float* __restrict__ b1,
                                                        const float* __restrict__ W2,
                                                        const float* __restrict__ b2) {
    extern __shared__ float smem[];
    float* Abase = smem;                    // NBUF x [64][AROW]
    float* Bbase = smem + NBUF * A_ST;      // NBUF x [32][BROW]

    const int t = threadIdx.x;
    const int m0 = blockIdx.x * 64;         // global row base (b*1024 + s0)
    const int warp = t >> 5, lane = t & 31;
    const int g = lane >> 2, tg = lane & 3;
    const int wm = (warp & 1) * 32;         // warp m offset
    const int wn = (warp >> 1) * 32;        // warp n offset

    // cp.async coords
    const int a_r0 = t >> 3, a_c = (t & 7) * 4;    // A: 64x32 = 512 chunks, 2/thread
    const int b_c = (t & 31) * 4;                  // B: 32x128 = 1024 chunks, 4/thread

    auto load_stage = [&](int buf, int s) {
        const int k0 = s * 32;
        float* A = Abase + buf * A_ST;
        float* B = Bbase + buf * B_ST;
        cpa16(&A[a_r0 * AROW + a_c],        &X[(size_t)(m0 + a_r0) * HID + k0 + a_c]);
        cpa16(&A[(a_r0 + 32) * AROW + a_c], &X[(size_t)(m0 + a_r0 + 32) * HID + k0 + a_c]);
#pragma unroll
        for (int u = 0; u < 4; u++) {
            int br = (t + 256 * u) >> 5;
            cpa16(&B[br * BROW + b_c], &W1[(size_t)(k0 + br) * D2 + b_c]);
        }
        cpa_commit();
    };

    float acc[2][4][4];   // [m16][n8][frag]
#pragma unroll
    for (int ni = 0; ni < 4; ni++) {
        float blo = b1[wn + ni * 8 + 2 * tg];
        float bhi = b1[wn + ni * 8 + 2 * tg + 1];
#pragma unroll
        for (int mi = 0; mi < 2; mi++) {
            acc[mi][ni][0] = blo; acc[mi][ni][1] = bhi;
            acc[mi][ni][2] = blo; acc[mi][ni][3] = bhi;
        }
    }

    const int NS = HID / 32;   // 32 stages
    load_stage(0, 0);
    load_stage(1, 1);
    load_stage(2, 2);

    for (int s = 0; s < NS; s++) {
        if (s + 3 < NS) { load_stage((s + 3) & 3, s + 3); cpa_wait<3>(); }
        else if (s + 2 < NS) cpa_wait<2>();
        else if (s + 1 < NS) cpa_wait<1>();
        else cpa_wait<0>();
        __syncthreads();

        const float* A = Abase + (s & 3) * A_ST;
        const float* B = Bbase + (s & 3) * B_ST;
#pragma unroll
        for (int kk = 0; kk < 32; kk += 8) {
            unsigned af[2][4];
#pragma unroll
            for (int mi = 0; mi < 2; mi++) {
                const int rb = wm + mi * 16;
                af[mi][0] = __float_as_uint(A[(rb + g) * AROW + kk + tg]);
                af[mi][1] = __float_as_uint(A[(rb + g + 8) * AROW + kk + tg]);
                af[mi][2] = __float_as_uint(A[(rb + g) * AROW + kk + tg + 4]);
                af[mi][3] = __float_as_uint(A[(rb + g + 8) * AROW + kk + tg + 4]);
            }
            unsigned bf[4][2];
#pragma unroll
            for (int ni = 0; ni < 4; ni++) {
                const int nn = wn + ni * 8 + g;
                bf[ni][0] = __float_as_uint(B[(kk + tg) * BROW + nn]);
                bf[ni][1] = __float_as_uint(B[(kk + tg + 4) * BROW + nn]);
            }
#pragma unroll
            for (int mi = 0; mi < 2; mi++)
#pragma unroll
                for (int ni = 0; ni < 4; ni++)
                    mma_tf32(acc[mi][ni], af[mi], bf[ni]);
        }
        __syncthreads();
    }

    // -------- epilogue: stash h tile in smem (reuse stage buffers) --------
    float* hs = smem;                 // [64][HROW]
    float* ws = smem + 64 * HROW;     // [128*24] W2
    __syncthreads();

#pragma unroll
    for (int mi = 0; mi < 2; mi++)
#pragma unroll
        for (int ni = 0; ni < 4; ni++) {
            const int row = wm + mi * 16 + g;
            const int col = wn + ni * 8 + 2 * tg;
            *(float2*)&hs[row * HROW + col]       = make_float2(acc[mi][ni][0], acc[mi][ni][1]);
            *(float2*)&hs[(row + 8) * HROW + col] = make_float2(acc[mi][ni][2], acc[mi][ni][3]);
        }
#pragma unroll
    for (int u = 0; u < 12; u++) ws[t + 256 * u] = W2[t + 256 * u];
    __syncthreads();

    const int b = m0 >> 10;
    const int s0 = m0 & 1023;
    const int sl = t & 63;            // row within tile
    const int dg = t >> 6;            // 0..3
    const int s = s0 + sl;
    const float* hrow = &hs[sl * HROW];

#pragma unroll
    for (int it = 0; it < 16; it++) {
        int d = dg + it * 4;          // 0..63
        int j = d >> 1;
        float inv = exp2f((float)(2 * j) * (-13.287712379549449f / 64.0f));
        float ang = (float)s * inv;
        float sn, cs;
        sincosf(ang, &sn, &cs);
        float qA = hrow[4 * j],     qB = hrow[4 * j + 2];
        float kA = hrow[4 * j + 1], kB = hrow[4 * j + 3];
        float qv, kv;
        if (d & 1) { qv = qB * cs + qA * sn; kv = kB * cs + kA * sn; }
        else       { qv = qA * cs - qB * sn; kv = kA * cs - kB * sn; }
        g_qT[(size_t)(b * 64 + d) * SEQ + s] = __float2bfloat16(qv * 0.125f);  // fold 1/sqrt(64)
        g_kT[(size_t)(b * 64 + d) * SEQ + s] = __float2bfloat16(kv);
    }

    for (int cc = dg; cc < NC; cc += 4) {
        float dot = b2[cc];
#pragma unroll
        for (int j = 0; j < D2; j += 4) {
            float4 h4 = *(const float4*)&hrow[j];
            dot += h4.x * ws[(j + 0) * NC + cc] + h4.y * ws[(j + 1) * NC + cc]
                 + h4.z * ws[(j + 2) * NC + cc] + h4.w * ws[(j + 3) * NC + cc];
        }
        g_bias[(size_t)(b * NC + cc) * SEQ + s] = __float2bfloat16(dot * 0.5f);
    }
}

// ---------------- kernel 2: logits (fill fast path + compute), bf16 staging ----------------
__global__ __launch_bounds__(256) void logits_kernel(const float* __restrict__ am,
                                                     float* __restrict__ out) {
    __shared__ float qs[64][64];
    __shared__ float ks[64][64];
    __shared__ float bq[NHEADS][64];
    __shared__ float bk[NHEADS][64];
    __shared__ float amm[64], amn[64];
    __shared__ int s_maskone;

    const int t = threadIdx.x;
    const int b = blockIdx.z, mt = blockIdx.y, nt = blockIdx.x;
    const int m0 = mt * 64, n0 = nt * 64;
    const int tm = t >> 4, tn = t & 15;
    const int ml = tm * 4, nl = tn * 4;

    if (t == 0) s_maskone = 1;
    if (t < 16)      *(float4*)&amm[t * 4]        = *(const float4*)&am[b * SEQ + m0 + t * 4];
    else if (t < 32) *(float4*)&amn[(t - 16) * 4] = *(const float4*)&am[b * SEQ + n0 + (t - 16) * 4];
    __syncthreads();
    if (t < 64 && (amm[t] != 1.0f || amn[t] != 1.0f)) s_maskone = 0;
    __syncthreads();
    const int maskone = s_maskone;

    // ---------- fast path: fully-masked tile -> constant ----------
    if (maskone && m0 > n0 + 63) {
        const float4 C4 = make_float4(CBIG, CBIG, CBIG, CBIG);
        for (int h = 0; h < NHEADS; h++) {
            size_t base = (((size_t)(b * NHEADS + h)) * SEQ + m0) * SEQ + n0;
#pragma unroll
            for (int i = 0; i < 4; i++) {
                int idx = t + 256 * i;
                int m = idx >> 4, n = (idx & 15) * 4;
                __stcs((float4*)(out + base + (size_t)m * SEQ + n), C4);
            }
        }
        return;
    }

    // ---------- slow path: stage bf16 -> fp32 smem ----------
#pragma unroll
    for (int u = 0; u < 4; u++) {
        int idx = t + 256 * u;
        int d = idx >> 4, mq = (idx & 15) * 4;
        uint2 qv = *(const uint2*)&g_qT[(size_t)(b * 64 + d) * SEQ + m0 + mq];
        uint2 kv = *(const uint2*)&g_kT[(size_t)(b * 64 + d) * SEQ + n0 + mq];
        *(float4*)&qs[d][mq] = bf4_to_f4(qv);
        *(float4*)&ks[d][mq] = bf4_to_f4(kv);
    }
    if (t < 192) {
        int h = t >> 4, mq = (t & 15) * 4;
        uint2 bqv = *(const uint2*)&g_bias[(size_t)(b * NC + 2 * h) * SEQ + m0 + mq];
        uint2 bkv = *(const uint2*)&g_bias[(size_t)(b * NC + 2 * h + 1) * SEQ + n0 + mq];
        *(float4*)&bq[h][mq] = bf4_to_f4(bqv);
        *(float4*)&bk[h][mq] = bf4_to_f4(bkv);
    }
    __syncthreads();

    u64 acc[4][2];
    u64 z = pack2(0.0f, 0.0f);
#pragma unroll
    for (int i = 0; i < 4; i++) { acc[i][0] = z; acc[i][1] = z; }

#pragma unroll 8
    for (int d = 0; d < 64; d++) {
        float4 q4 = *(float4*)&qs[d][ml];
        ulonglong2 kp = *(const ulonglong2*)&ks[d][nl];
        u64 q0 = pack2(q4.x, q4.x), q1 = pack2(q4.y, q4.y);
        u64 q2 = pack2(q4.z, q4.z), q3 = pack2(q4.w, q4.w);
        fma2(acc[0][0], q0, kp.x); fma2(acc[0][1], q0, kp.y);
        fma2(acc[1][0], q1, kp.x); fma2(acc[1][1], q1, kp.y);
        fma2(acc[2][0], q2, kp.x); fma2(acc[2][1], q2, kp.y);
        fma2(acc[3][0], q3, kp.x); fma2(acc[3][1], q3, kp.y);
    }

    float att[4][4];
#pragma unroll
    for (int i = 0; i < 4; i++) {
        unpack2(acc[i][0], att[i][0], att[i][1]);
        unpack2(acc[i][1], att[i][2], att[i][3]);
    }

    const float BIG = 1e12f;
#pragma unroll
    for (int i = 0; i < 4; i++) {
        int gm = m0 + ml + i;
#pragma unroll
        for (int j = 0; j < 4; j++) {
            int gn = n0 + nl + j;
            if (!maskone) att[i][j] -= (1.0f - amm[ml + i] * amn[nl + j]) * BIG;
            if (gm > gn) att[i][j] -= BIG;
        }
    }

    const bool rowzero = (m0 == 0 && tm == 0);
    const bool colzero = (n0 == 0 && tn == 0);
    const float NEG = -10000.0f;

    for (int h = 0; h < NHEADS; h++) {
        size_t base = (((size_t)(b * NHEADS + h)) * SEQ + m0) * SEQ + n0;
        float4 bkv = *(float4*)&bk[h][nl];
#pragma unroll
        for (int i = 0; i < 4; i++) {
            float bb = bq[h][ml + i];
            float4 v;
            v.x = att[i][0] + bb + bkv.x;
            v.y = att[i][1] + bb + bkv.y;
            v.z = att[i][2] + bb + bkv.z;
            v.w = att[i][3] + bb + bkv.w;
            if (rowzero && i == 0) { v.x = NEG; v.y = NEG; v.z = NEG; v.w = NEG; }
            if (colzero) v.x = (m0 + ml + i == 0) ? NEG : CBIG;
            __stcs((float4*)(out + base + (size_t)(ml + i) * SEQ + nl), v);
        }
    }
}

// ---------------- launch ----------------
extern "C" void kernel_launch(void* const* d_in, const int* in_sizes, int n_in,
                              void* d_out, int out_size) {
    const float* X  = (const float*)d_in[0];
    const float* am = (const float*)d_in[1];
    const float* W1 = (const float*)d_in[2];
    const float* b1 = (const float*)d_in[3];
    const float* W2 = (const float*)d_in[4];
    const float* b2 = (const float*)d_in[5];
    float* out = (float*)d_out;

    cudaFuncSetAttribute(gemm_rope_kernel,
                         cudaFuncAttributeMaxDynamicSharedMemorySize,
                         SMEM_FLOATS * 4);
    gemm_rope_kernel<<<(BATCH * SEQ) / 64, 256, SMEM_FLOATS * 4>>>(X, W1, b1, W2, b2);
    dim3 g3(SEQ / 64, SEQ / 64, BATCH);
    logits_kernel<<<g3, 256>>>(am, out);
}

// round 13
// speedup vs baseline: 1.2013x; 1.0053x over previous
#include <cuda_runtime.h>
#include <cuda_bf16.h>

#define BATCH 8
#define SEQ 1024
#define HID 1024
#define D2 128
#define NHEADS 12
#define NC 24

typedef unsigned long long u64;

// ---------------- scratch (device globals; no allocation) ----------------
__device__ __nv_bfloat16 g_qT[BATCH * 64 * SEQ];    // [b][d][s], pre-scaled by 1/8
__device__ __nv_bfloat16 g_kT[BATCH * 64 * SEQ];    // [b][d][s]
__device__ __nv_bfloat16 g_bias[BATCH * NC * SEQ];  // [b][c][s], already (h@W2+b2)/2

// ---------------- f32x2 helpers ----------------
__device__ __forceinline__ u64 pack2(float lo, float hi) {
    u64 r; asm("mov.b64 %0, {%1,%2};" : "=l"(r) : "f"(lo), "f"(hi)); return r;
}
__device__ __forceinline__ void unpack2(u64 v, float& lo, float& hi) {
    asm("mov.b64 {%0,%1}, %2;" : "=f"(lo), "=f"(hi) : "l"(v));
}
__device__ __forceinline__ void fma2(u64& d, u64 a, u64 b) {
    asm("fma.rn.f32x2 %0, %1, %2, %0;" : "+l"(d) : "l"(a), "l"(b));
}

// ---------------- cp.async helpers ----------------
__device__ __forceinline__ void cpa16(void* s, const void* g) {
    unsigned sa = (unsigned)__cvta_generic_to_shared(s);
    asm volatile("cp.async.cg.shared.global [%0], [%1], 16;\n" :: "r"(sa), "l"(g));
}
__device__ __forceinline__ void cpa_commit() { asm volatile("cp.async.commit_group;\n" ::: "memory"); }
template<int N> __device__ __forceinline__ void cpa_wait() {
    asm volatile("cp.async.wait_group %0;\n" :: "n"(N) : "memory");
}

// ---------------- tf32 mma ----------------
__device__ __forceinline__ void mma_tf32(float* d, const unsigned* a, const unsigned* b) {
    asm volatile("mma.sync.aligned.m16n8k8.row.col.f32.tf32.tf32.f32 "
        "{%0,%1,%2,%3}, {%4,%5,%6,%7}, {%8,%9}, {%0,%1,%2,%3};"
        : "+f"(d[0]), "+f"(d[1]), "+f"(d[2]), "+f"(d[3])
        : "r"(a[0]), "r"(a[1]), "r"(a[2]), "r"(a[3]), "r"(b[0]), "r"(b[1]));
}

// bf16x4 (as uint2) -> float4
__device__ __forceinline__ float4 bf4_to_f4(uint2 v) {
    __nv_bfloat162 p0 = *reinterpret_cast<__nv_bfloat162*>(&v.x);
    __nv_bfloat162 p1 = *reinterpret_cast<__nv_bfloat162*>(&v.y);
    float2 f0 = __bfloat1622float2(p0);
    float2 f1 = __bfloat1622float2(p1);
    return make_float4(f0.x, f0.y, f1.x, f1.y);
}

// smem geometry (floats) — M-tile 64, 256 threads, K-stage 64, NBUF=3
#define AROW 68                     // 64 + 4 pad (conflict-free A gather)
#define BROW 136                    // 128 + 8 pad (conflict-free B gather)
#define A_ST (64 * AROW)            // 4352
#define B_ST (64 * BROW)            // 8704
#define NBUF 3
#define SMEM_FLOATS (NBUF * (A_ST + B_ST))   // 39168 floats = 156672 B
#define HROW 132

// -1e12 in fp32 = -999999995904; adding |x|<32768 rounds back to it exactly.
#define CBIG -999999995904.0f

// ---------------- kernel 1: fused h=X@W1+b1 -> RoPE(q,k)T + bias (bf16 out) ----------------
// 256 threads (8 warps, 2m x 4n; warp tile 32x32), M-tile 64, K staged x64, 3-buf (prefetch 2).
__global__ __launch_bounds__(256) void gemm_rope_kernel(const float* __restrict__ X,
                                                        const float* __restrict__ W1,
                                                        const float* __restrict__ b1,
                                                        const float* __restrict__ W2,
                                                        const float* __restrict__ b2) {
    extern __shared__ float smem[];
    float* Abase = smem;                    // NBUF x [64][AROW]
    float* Bbase = smem + NBUF * A_ST;      // NBUF x [64][BROW]

    const int t = threadIdx.x;
    const int m0 = blockIdx.x * 64;         // global row base (b*1024 + s0)
    const int warp = t >> 5, lane = t & 31;
    const int g = lane >> 2, tg = lane & 3;
    const int wm = (warp & 1) * 32;         // warp m offset
    const int wn = (warp >> 1) * 32;        // warp n offset

    // cp.async coords — K-stage 64
    // A: 64 rows x 64 cols = 1024 16B-chunks, 4/thread
    // B: 64 rows x 128 cols = 2048 chunks, 8/thread
    auto load_stage = [&](int buf, int s) {
        const int k0 = s * 64;
        float* A = Abase + buf * A_ST;
        float* B = Bbase + buf * B_ST;
#pragma unroll
        for (int u = 0; u < 4; u++) {
            int id = t + 256 * u;
            int ar = id >> 4, ac = (id & 15) * 4;
            cpa16(&A[ar * AROW + ac], &X[(size_t)(m0 + ar) * HID + k0 + ac]);
        }
#pragma unroll
        for (int u = 0; u < 8; u++) {
            int id = t + 256 * u;
            int br = id >> 5, bc = (id & 31) * 4;
            cpa16(&B[br * BROW + bc], &W1[(size_t)(k0 + br) * D2 + bc]);
        }
        cpa_commit();
    };

    float acc[2][4][4];   // [m16][n8][frag]
#pragma unroll
    for (int ni = 0; ni < 4; ni++) {
        float blo = b1[wn + ni * 8 + 2 * tg];
        float bhi = b1[wn + ni * 8 + 2 * tg + 1];
#pragma unroll
        for (int mi = 0; mi < 2; mi++) {
            acc[mi][ni][0] = blo; acc[mi][ni][1] = bhi;
            acc[mi][ni][2] = blo; acc[mi][ni][3] = bhi;
        }
    }

    const int NS = HID / 64;   // 16 stages
    load_stage(0, 0);
    load_stage(1, 1);

    for (int s = 0; s < NS; s++) {
        if (s + 2 < NS) { load_stage((s + 2) % 3, s + 2); cpa_wait<2>(); }
        else if (s + 1 < NS) cpa_wait<1>();
        else cpa_wait<0>();
        __syncthreads();

        const float* A = Abase + (s % 3) * A_ST;
        const float* B = Bbase + (s % 3) * B_ST;
#pragma unroll
        for (int kk = 0; kk < 64; kk += 8) {
            unsigned af[2][4];
#pragma unroll
            for (int mi = 0; mi < 2; mi++) {
                const int rb = wm + mi * 16;
                af[mi][0] = __float_as_uint(A[(rb + g) * AROW + kk + tg]);
                af[mi][1] = __float_as_uint(A[(rb + g + 8) * AROW + kk + tg]);
                af[mi][2] = __float_as_uint(A[(rb + g) * AROW + kk + tg + 4]);
                af[mi][3] = __float_as_uint(A[(rb + g + 8) * AROW + kk + tg + 4]);
            }
            unsigned bf[4][2];
#pragma unroll
            for (int ni = 0; ni < 4; ni++) {
                const int nn = wn + ni * 8 + g;
                bf[ni][0] = __float_as_uint(B[(kk + tg) * BROW + nn]);
                bf[ni][1] = __float_as_uint(B[(kk + tg + 4) * BROW + nn]);
            }
#pragma unroll
            for (int mi = 0; mi < 2; mi++)
#pragma unroll
                for (int ni = 0; ni < 4; ni++)
                    mma_tf32(acc[mi][ni], af[mi], bf[ni]);
        }
        __syncthreads();
    }

    // -------- epilogue: stash h tile in smem (reuse stage buffers) --------
    float* hs = smem;                 // [64][HROW]
    float* ws = smem + 64 * HROW;     // [128*24] W2
    __syncthreads();

#pragma unroll
    for (int mi = 0; mi < 2; mi++)
#pragma unroll
        for (int ni = 0; ni < 4; ni++) {
            const int row = wm + mi * 16 + g;
            const int col = wn + ni * 8 + 2 * tg;
            *(float2*)&hs[row * HROW + col]       = make_float2(acc[mi][ni][0], acc[mi][ni][1]);
            *(float2*)&hs[(row + 8) * HROW + col] = make_float2(acc[mi][ni][2], acc[mi][ni][3]);
        }
#pragma unroll
    for (int u = 0; u < 12; u++) ws[t + 256 * u] = W2[t + 256 * u];
    __syncthreads();

    const int b = m0 >> 10;
    const int s0 = m0 & 1023;
    const int sl = t & 63;            // row within tile
    const int dg = t >> 6;            // 0..3
    const int s = s0 + sl;
    const float* hrow = &hs[sl * HROW];

#pragma unroll
    for (int it = 0; it < 16; it++) {
        int d = dg + it * 4;          // 0..63
        int j = d >> 1;
        float inv = exp2f((float)(2 * j) * (-13.287712379549449f / 64.0f));
        float ang = (float)s * inv;
        float sn, cs;
        sincosf(ang, &sn, &cs);
        float qA = hrow[4 * j],     qB = hrow[4 * j + 2];
        float kA = hrow[4 * j + 1], kB = hrow[4 * j + 3];
        float qv, kv;
        if (d & 1) { qv = qB * cs + qA * sn; kv = kB * cs + kA * sn; }
        else       { qv = qA * cs - qB * sn; kv = kA * cs - kB * sn; }
        g_qT[(size_t)(b * 64 + d) * SEQ + s] = __float2bfloat16(qv * 0.125f);  // fold 1/sqrt(64)
        g_kT[(size_t)(b * 64 + d) * SEQ + s] = __float2bfloat16(kv);
    }

    for (int cc = dg; cc < NC; cc += 4) {
        float dot = b2[cc];
#pragma unroll
        for (int j = 0; j < D2; j += 4) {
            float4 h4 = *(const float4*)&hrow[j];
            dot += h4.x * ws[(j + 0) * NC + cc] + h4.y * ws[(j + 1) * NC + cc]
                 + h4.z * ws[(j + 2) * NC + cc] + h4.w * ws[(j + 3) * NC + cc];
        }
        g_bias[(size_t)(b * NC + cc) * SEQ + s] = __float2bfloat16(dot * 0.5f);
    }
}

// ---------------- kernel 2: logits (fill fast path + compute), bf16 staging ----------------
__global__ __launch_bounds__(256) void logits_kernel(const float* __restrict__ am,
                                                     float* __restrict__ out) {
    __shared__ float qs[64][64];
    __shared__ float ks[64][64];
    __shared__ float bq[NHEADS][64];
    __shared__ float bk[NHEADS][64];
    __shared__ float amm[64], amn[64];
    __shared__ int s_maskone;

    const int t = threadIdx.x;
    const int b = blockIdx.z, mt = blockIdx.y, nt = blockIdx.x;
    const int m0 = mt * 64, n0 = nt * 64;
    const int tm = t >> 4, tn = t & 15;
    const int ml = tm * 4, nl = tn * 4;

    if (t == 0) s_maskone = 1;
    if (t < 16)      *(float4*)&amm[t * 4]        = *(const float4*)&am[b * SEQ + m0 + t * 4];
    else if (t < 32) *(float4*)&amn[(t - 16) * 4] = *(const float4*)&am[b * SEQ + n0 + (t - 16) * 4];
    __syncthreads();
    if (t < 64 && (amm[t] != 1.0f || amn[t] != 1.0f)) s_maskone = 0;
    __syncthreads();
    const int maskone = s_maskone;

    // ---------- fast path: fully-masked tile -> constant ----------
    if (maskone && m0 > n0 + 63) {
        const float4 C4 = make_float4(CBIG, CBIG, CBIG, CBIG);
        for (int h = 0; h < NHEADS; h++) {
            size_t base = (((size_t)(b * NHEADS + h)) * SEQ + m0) * SEQ + n0;
#pragma unroll
            for (int i = 0; i < 4; i++) {
                int idx = t + 256 * i;
                int m = idx >> 4, n = (idx & 15) * 4;
                __stcs((float4*)(out + base + (size_t)m * SEQ + n), C4);
            }
        }
        return;
    }

    // ---------- slow path: stage bf16 -> fp32 smem ----------
#pragma unroll
    for (int u = 0; u < 4; u++) {
        int idx = t + 256 * u;
        int d = idx >> 4, mq = (idx & 15) * 4;
        uint2 qv = *(const uint2*)&g_qT[(size_t)(b * 64 + d) * SEQ + m0 + mq];
        uint2 kv = *(const uint2*)&g_kT[(size_t)(b * 64 + d) * SEQ + n0 + mq];
        *(float4*)&qs[d][mq] = bf4_to_f4(qv);
        *(float4*)&ks[d][mq] = bf4_to_f4(kv);
    }
    if (t < 192) {
        int h = t >> 4, mq = (t & 15) * 4;
        uint2 bqv = *(const uint2*)&g_bias[(size_t)(b * NC + 2 * h) * SEQ + m0 + mq];
        uint2 bkv = *(const uint2*)&g_bias[(size_t)(b * NC + 2 * h + 1) * SEQ + n0 + mq];
        *(float4*)&bq[h][mq] = bf4_to_f4(bqv);
        *(float4*)&bk[h][mq] = bf4_to_f4(bkv);
    }
    __syncthreads();

    u64 acc[4][2];
    u64 z = pack2(0.0f, 0.0f);
#pragma unroll
    for (int i = 0; i < 4; i++) { acc[i][0] = z; acc[i][1] = z; }

#pragma unroll 8
    for (int d = 0; d < 64; d++) {
        float4 q4 = *(float4*)&qs[d][ml];
        ulonglong2 kp = *(const ulonglong2*)&ks[d][nl];
        u64 q0 = pack2(q4.x, q4.x), q1 = pack2(q4.y, q4.y);
        u64 q2 = pack2(q4.z, q4.z), q3 = pack2(q4.w, q4.w);
        fma2(acc[0][0], q0, kp.x); fma2(acc[0][1], q0, kp.y);
        fma2(acc[1][0], q1, kp.x); fma2(acc[1][1], q1, kp.y);
        fma2(acc[2][0], q2, kp.x); fma2(acc[2][1], q2, kp.y);
        fma2(acc[3][0], q3, kp.x); fma2(acc[3][1], q3, kp.y);
    }

    float att[4][4];
#pragma unroll
    for (int i = 0; i < 4; i++) {
        unpack2(acc[i][0], att[i][0], att[i][1]);
        unpack2(acc[i][1], att[i][2], att[i][3]);
    }

    const float BIG = 1e12f;
#pragma unroll
    for (int i = 0; i < 4; i++) {
        int gm = m0 + ml + i;
#pragma unroll
        for (int j = 0; j < 4; j++) {
            int gn = n0 + nl + j;
            if (!maskone) att[i][j] -= (1.0f - amm[ml + i] * amn[nl + j]) * BIG;
            if (gm > gn) att[i][j] -= BIG;
        }
    }

    const bool rowzero = (m0 == 0 && tm == 0);
    const bool colzero = (n0 == 0 && tn == 0);
    const float NEG = -10000.0f;

    for (int h = 0; h < NHEADS; h++) {
        size_t base = (((size_t)(b * NHEADS + h)) * SEQ + m0) * SEQ + n0;
        float4 bkv = *(float4*)&bk[h][nl];
#pragma unroll
        for (int i = 0; i < 4; i++) {
            float bb = bq[h][ml + i];
            float4 v;
            v.x = att[i][0] + bb + bkv.x;
            v.y = att[i][1] + bb + bkv.y;
            v.z = att[i][2] + bb + bkv.z;
            v.w = att[i][3] + bb + bkv.w;
            if (rowzero && i == 0) { v.x = NEG; v.y = NEG; v.z = NEG; v.w = NEG; }
            if (colzero) v.x = (m0 + ml + i == 0) ? NEG : CBIG;
            __stcs((float4*)(out + base + (size_t)(ml + i) * SEQ + nl), v);
        }
    }
}

// ---------------- launch ----------------
extern "C" void kernel_launch(void* const* d_in, const int* in_sizes, int n_in,
                              void* d_out, int out_size) {
    const float* X  = (const float*)d_in[0];
    const float* am = (const float*)d_in[1];
    const float* W1 = (const float*)d_in[2];
    const float* b1 = (const float*)d_in[3];
    const float* W2 = (const float*)d_in[4];
    const float* b2 = (const float*)d_in[5];
    float* out = (float*)d_out;

    cudaFuncSetAttribute(gemm_rope_kernel,
                         cudaFuncAttributeMaxDynamicSharedMemorySize,
                         SMEM_FLOATS * 4);
    gemm_rope_kernel<<<(BATCH * SEQ) / 64, 256, SMEM_FLOATS * 4>>>(X, W1, b1, W2, b2);
    dim3 g3(SEQ / 64, SEQ / 64, BATCH);
    logits_kernel<<<g3, 256>>>(am, out);
}